// round 3
// baseline (speedup 1.0000x reference)
#include <cuda_runtime.h>
#include <cuda_bf16.h>
#include <math.h>
#include <stdint.h>

// ---------------- problem constants ----------------
#define DD    768
#define SS    1024
#define BB    4
#define LL    12
#define HH    12
#define HSZ   64
#define VV    32000
#define MR    (BB*SS)        // 4096 rows
#define QKVN  (3*DD)         // 2304
#define FF1   (4*DD)         // 3072
#define FF2   (3*DD)         // 2304
#define INV_SQRT_D 0.03608439182435161f   // 1/sqrt(768)
#define INV_SQRT_HS 0.125f                // 1/sqrt(64)

typedef __nv_bfloat16 bf16;

// ---------------- scratch (device globals; no allocs) ----------------
__device__ float g_x   [MR*DD];
__device__ float g_qkv [MR*QKVN];
__device__ float g_loss_sum;

// activation hi/lo pairs
__device__ bf16 g_h_h [MR*DD],  g_h_l [MR*DD];
__device__ bf16 g_o_h [MR*DD],  g_o_l [MR*DD];
__device__ bf16 g_f1_h[MR*FF1], g_f1_l[MR*FF1];
__device__ bf16 g_f2_h[MR*FF2], g_f2_l[MR*FF2];

// weight hi/lo pairs
__device__ bf16 g_Wqkv_h[LL*DD*QKVN], g_Wqkv_l[LL*DD*QKVN];
__device__ bf16 g_Wo_h [LL*DD*DD],    g_Wo_l [LL*DD*DD];
__device__ bf16 g_W1_h [LL*DD*FF1],   g_W1_l [LL*DD*FF1];
__device__ bf16 g_W2_h [LL*FF1*FF2],  g_W2_l [LL*FF1*FF2];
__device__ bf16 g_W3_h [LL*FF2*DD],   g_W3_l [LL*FF2*DD];
__device__ bf16 g_tok_h[VV*DD],       g_tok_l[VV*DD];
__device__ float g_bqkv[LL*QKVN];

// ---------------- helpers ----------------
__device__ __forceinline__ float gelu_exact(float v) {
    return 0.5f * v * (1.0f + erff(v * 0.70710678118654752f));
}

__device__ __forceinline__ void split2(float v, bf16& hi, bf16& lo) {
    hi = __float2bfloat16_rn(v);
    lo = __float2bfloat16_rn(v - __bfloat162float(hi));
}

__device__ __forceinline__ void cp_async16(uint32_t dst, const void* src) {
    asm volatile("cp.async.cg.shared.global [%0], [%1], 16;\n" :: "r"(dst), "l"(src));
}
__device__ __forceinline__ void cp_commit() {
    asm volatile("cp.async.commit_group;\n" ::: "memory");
}

__device__ __forceinline__ void ldsm4(uint32_t addr, uint32_t& r0, uint32_t& r1,
                                      uint32_t& r2, uint32_t& r3) {
    asm volatile("ldmatrix.sync.aligned.m8n8.x4.shared.b16 {%0,%1,%2,%3}, [%4];"
                 : "=r"(r0), "=r"(r1), "=r"(r2), "=r"(r3) : "r"(addr));
}
__device__ __forceinline__ void ldsm4t(uint32_t addr, uint32_t& r0, uint32_t& r1,
                                       uint32_t& r2, uint32_t& r3) {
    asm volatile("ldmatrix.sync.aligned.m8n8.x4.trans.shared.b16 {%0,%1,%2,%3}, [%4];"
                 : "=r"(r0), "=r"(r1), "=r"(r2), "=r"(r3) : "r"(addr));
}

__device__ __forceinline__ void mma_bf16(float* d, uint32_t a0, uint32_t a1,
                                         uint32_t a2, uint32_t a3,
                                         uint32_t b0, uint32_t b1) {
    asm volatile(
        "mma.sync.aligned.m16n8k16.row.col.f32.bf16.bf16.f32 "
        "{%0,%1,%2,%3}, {%4,%5,%6,%7}, {%8,%9}, {%0,%1,%2,%3};\n"
        : "+f"(d[0]), "+f"(d[1]), "+f"(d[2]), "+f"(d[3])
        : "r"(a0), "r"(a1), "r"(a2), "r"(a3), "r"(b0), "r"(b1));
}

// ---------------- weight split / packing ----------------
__global__ void split_k(const float* __restrict__ src, bf16* __restrict__ h,
                        bf16* __restrict__ l, long n) {
    long i = (long)blockIdx.x * blockDim.x + threadIdx.x;
    if (i >= n) return;
    bf16 hi, lo; split2(src[i], hi, lo);
    h[i] = hi; l[i] = lo;
}

__global__ void pack_qkv_w(const float* __restrict__ Wq, const float* __restrict__ Wk,
                           const float* __restrict__ Wv,
                           bf16* __restrict__ Wph, bf16* __restrict__ Wpl) {
    long i = (long)blockIdx.x * blockDim.x + threadIdx.x;
    long total = (long)LL * DD * QKVN;
    if (i >= total) return;
    int c = (int)(i % QKVN);
    long rem = i / QKVN;
    int d = (int)(rem % DD);
    int l = (int)(rem / DD);
    int which = c / DD;
    int ce = c % DD;
    int h = ce / HSZ;
    int e = ce % HSZ;
    const float* W = (which == 0) ? Wq : (which == 1) ? Wk : Wv;
    float v = W[(((long)l*HH + h)*DD + d)*HSZ + e];
    bf16 hi, lo; split2(v, hi, lo);
    Wph[i] = hi; Wpl[i] = lo;
}

__global__ void pack_qkv_b(const float* __restrict__ bq, const float* __restrict__ bk,
                           const float* __restrict__ bv, float* __restrict__ bp) {
    int i = blockIdx.x * blockDim.x + threadIdx.x;
    if (i >= LL*QKVN) return;
    int c = i % QKVN;
    int l = i / QKVN;
    int which = c / DD;
    int ce = c % DD;
    int h = ce / HSZ;
    int e = ce % HSZ;
    const float* b = (which == 0) ? bq : (which == 1) ? bk : bv;
    bp[i] = b[((long)l*HH + h)*HSZ + e];
}

// ---------------- embedding ----------------
__global__ void embed_k(const int* __restrict__ idx, const float* __restrict__ tok,
                        const float* __restrict__ pos, float* __restrict__ x) {
    long i = (long)blockIdx.x * blockDim.x + threadIdx.x;
    if (i >= (long)MR*DD) return;
    int d = (int)(i % DD);
    int r = (int)(i / DD);
    int s = r & (SS - 1);
    x[i] = tok[(long)idx[r]*DD + d] + pos[(long)s*DD + d] * INV_SQRT_D;
}

// ---------------- layernorm (one block per row) -> hi/lo bf16 ----------------
__global__ __launch_bounds__(256)
void layernorm_k(const float* __restrict__ in, bf16* __restrict__ outh,
                 bf16* __restrict__ outl,
                 const float* __restrict__ gamma, const float* __restrict__ beta) {
    int row = blockIdx.x;
    int tid = threadIdx.x;
    const float* xr = in + (long)row*DD;
    float v0 = xr[tid], v1 = xr[tid+256], v2 = xr[tid+512];
    float s = v0+v1+v2;
    float q = v0*v0 + v1*v1 + v2*v2;
    __shared__ float sm[16];
    #pragma unroll
    for (int off = 16; off > 0; off >>= 1) {
        s += __shfl_xor_sync(0xffffffffu, s, off);
        q += __shfl_xor_sync(0xffffffffu, q, off);
    }
    int warp = tid >> 5, lane = tid & 31;
    if (lane == 0) { sm[warp] = s; sm[warp+8] = q; }
    __syncthreads();
    if (tid < 32) {
        float ss = (lane < 8) ? sm[lane] : 0.f;
        float qq = (lane < 8) ? sm[lane+8] : 0.f;
        #pragma unroll
        for (int off = 4; off > 0; off >>= 1) {
            ss += __shfl_xor_sync(0xffffffffu, ss, off);
            qq += __shfl_xor_sync(0xffffffffu, qq, off);
        }
        if (lane == 0) {
            float mu = ss * (1.0f/768.0f);
            float var = qq * (1.0f/768.0f) - mu*mu;
            sm[0] = mu;
            sm[1] = rsqrtf(var + 1e-5f);
        }
    }
    __syncthreads();
    float mu = sm[0], rs = sm[1];
    long base = (long)row*DD;
    #pragma unroll
    for (int p = 0; p < 3; p++) {
        int c = tid + p*256;
        float v = (p == 0) ? v0 : (p == 1) ? v1 : v2;
        float y = (v-mu)*rs*gamma[c] + beta[c];
        bf16 hi, lo; split2(y, hi, lo);
        outh[base + c] = hi; outl[base + c] = lo;
    }
}

// ------------- bf16 split tensor-core GEMM: 128x128 tile, 8 warps -------------
// C = (Ah+Al) @ (Bh+Bl) approx, fp32 accum, 3 MMA terms.
// EPI: 0 = +bias -> f32 C ; 1 = gelu(+bias) -> hi/lo bf16 (Ch, Cl)
//      2 = resid + scale*(acc+bias) -> f32 C ; 3 = plain -> f32 C
// TRB: B arrays are [N,K] row-major; else [K,N] row-major.
#define APAD 24     // row stride (elems) for [128][16] tiles
#define BPAD 136    // row stride (elems) for [16][128] tiles
template<int EPI, bool TRB>
__global__ __launch_bounds__(256)
void bgemm_k(const bf16* __restrict__ Ah, const bf16* __restrict__ Al,
             const bf16* __restrict__ Bh, const bf16* __restrict__ Bl,
             const float* __restrict__ bias, float* __restrict__ C,
             bf16* __restrict__ Ch, bf16* __restrict__ Cl,
             const float* __restrict__ resid, const float* __restrict__ scale_p,
             int M, int N, int K) {
    __shared__ bf16 As[2][2][128*APAD];
    __shared__ bf16 Bs[2][2][TRB ? (128*APAD) : (16*BPAD)];

    const int tid  = threadIdx.x;
    const int bm   = blockIdx.y, bn = blockIdx.x;
    const int warp = tid >> 5, lane = tid & 31;
    const int wm   = warp >> 1, wn = warp & 1;      // 4x2 warp grid, warp = 32x64
    const int g    = lane >> 2, tg = lane & 3;
    const int lt   = lane >> 3, lrow = lane & 7;    // ldmatrix tile / row-in-tile

    // cp.async indices: A-style tiles ([128 rows][16 cols]): row = tid>>1, chunk = tid&1
    const int arow = tid >> 1, achk = (tid & 1) * 8;
    // B non-TRB ([16 rows][128 cols]): row = tid>>4, chunk col = (tid&15)*8
    const int brow = tid >> 4, bchk = (tid & 15) * 8;

    float acc[2][8][4];
    #pragma unroll
    for (int mi = 0; mi < 2; mi++)
        #pragma unroll
        for (int ni = 0; ni < 8; ni++)
            #pragma unroll
            for (int v = 0; v < 4; v++) acc[mi][ni][v] = 0.f;

    const int nsteps = K >> 4;

    auto issue = [&](int s, int buf) {
        int k0 = s << 4;
        {
            uint32_t d0 = (uint32_t)__cvta_generic_to_shared(&As[buf][0][arow*APAD + achk]);
            uint32_t d1 = (uint32_t)__cvta_generic_to_shared(&As[buf][1][arow*APAD + achk]);
            const bf16* s0 = Ah + (long)(bm*128 + arow)*K + k0 + achk;
            const bf16* s1 = Al + (long)(bm*128 + arow)*K + k0 + achk;
            cp_async16(d0, s0);
            cp_async16(d1, s1);
        }
        if (TRB) {
            uint32_t d0 = (uint32_t)__cvta_generic_to_shared(&Bs[buf][0][arow*APAD + achk]);
            uint32_t d1 = (uint32_t)__cvta_generic_to_shared(&Bs[buf][1][arow*APAD + achk]);
            const bf16* s0 = Bh + (long)(bn*128 + arow)*K + k0 + achk;
            const bf16* s1 = Bl + (long)(bn*128 + arow)*K + k0 + achk;
            cp_async16(d0, s0);
            cp_async16(d1, s1);
        } else {
            uint32_t d0 = (uint32_t)__cvta_generic_to_shared(&Bs[buf][0][brow*BPAD + bchk]);
            uint32_t d1 = (uint32_t)__cvta_generic_to_shared(&Bs[buf][1][brow*BPAD + bchk]);
            const bf16* s0 = Bh + (long)(k0 + brow)*N + bn*128 + bchk;
            const bf16* s1 = Bl + (long)(k0 + brow)*N + bn*128 + bchk;
            cp_async16(d0, s0);
            cp_async16(d1, s1);
        }
        cp_commit();
    };

    issue(0, 0);
    int buf = 0;
    for (int s = 0; s < nsteps; s++) {
        if (s + 1 < nsteps) {
            issue(s + 1, buf ^ 1);
            asm volatile("cp.async.wait_group 1;\n" ::: "memory");
        } else {
            asm volatile("cp.async.wait_group 0;\n" ::: "memory");
        }
        __syncthreads();

        // A fragments: hi & lo, 2 m16 tiles per warp
        uint32_t fah[2][4], fal[2][4];
        #pragma unroll
        for (int mi = 0; mi < 2; mi++) {
            int row = wm*32 + mi*16 + (lt & 1)*8 + lrow;
            int col = (lt >> 1) * 8;
            uint32_t ah = (uint32_t)__cvta_generic_to_shared(&As[buf][0][row*APAD + col]);
            uint32_t al = (uint32_t)__cvta_generic_to_shared(&As[buf][1][row*APAD + col]);
            ldsm4(ah, fah[mi][0], fah[mi][1], fah[mi][2], fah[mi][3]);
            ldsm4(al, fal[mi][0], fal[mi][1], fal[mi][2], fal[mi][3]);
        }

        #pragma unroll
        for (int gi = 0; gi < 4; gi++) {
            uint32_t bh[4], bl[4];
            if (TRB) {
                int row = wn*64 + gi*16 + (lt & 1)*8 + lrow;
                int col = (lt >> 1) * 8;
                uint32_t a0 = (uint32_t)__cvta_generic_to_shared(&Bs[buf][0][row*APAD + col]);
                uint32_t a1 = (uint32_t)__cvta_generic_to_shared(&Bs[buf][1][row*APAD + col]);
                ldsm4(a0, bh[0], bh[1], bh[2], bh[3]);
                ldsm4(a1, bl[0], bl[1], bl[2], bl[3]);
                // frag nblk0 = {r0, r2}; nblk1 = {r1, r3}
                uint32_t t;
                t = bh[1]; bh[1] = bh[2]; bh[2] = t;
                t = bl[1]; bl[1] = bl[2]; bl[2] = t;
            } else {
                int row = (lt & 1)*8 + lrow;
                int col = wn*64 + gi*16 + (lt >> 1)*8;
                uint32_t a0 = (uint32_t)__cvta_generic_to_shared(&Bs[buf][0][row*BPAD + col]);
                uint32_t a1 = (uint32_t)__cvta_generic_to_shared(&Bs[buf][1][row*BPAD + col]);
                ldsm4t(a0, bh[0], bh[1], bh[2], bh[3]);
                ldsm4t(a1, bl[0], bl[1], bl[2], bl[3]);
                // frag nblk0 = {r0, r1}; nblk1 = {r2, r3}
            }
            #pragma unroll
            for (int blk = 0; blk < 2; blk++) {
                int ni = gi*2 + blk;
                uint32_t b0h = bh[blk*2], b1h = bh[blk*2+1];
                uint32_t b0l = bl[blk*2], b1l = bl[blk*2+1];
                #pragma unroll
                for (int mi = 0; mi < 2; mi++) {
                    mma_bf16(acc[mi][ni], fah[mi][0], fah[mi][1], fah[mi][2], fah[mi][3], b0h, b1h);
                    mma_bf16(acc[mi][ni], fah[mi][0], fah[mi][1], fah[mi][2], fah[mi][3], b0l, b1l);
                    mma_bf16(acc[mi][ni], fal[mi][0], fal[mi][1], fal[mi][2], fal[mi][3], b0h, b1h);
                }
            }
        }
        __syncthreads();
        buf ^= 1;
    }

    // ---------------- epilogue ----------------
    float scale = (EPI == 2) ? *scale_p : 0.f;
    #pragma unroll
    for (int mi = 0; mi < 2; mi++) {
        #pragma unroll
        for (int ni = 0; ni < 8; ni++) {
            int r0 = bm*128 + wm*32 + mi*16 + g;
            int c  = bn*128 + wn*64 + ni*8 + 2*tg;
            float2 bval = make_float2(0.f, 0.f);
            if (EPI == 0 || EPI == 1 || EPI == 2) bval = *(const float2*)(bias + c);
            #pragma unroll
            for (int half = 0; half < 2; half++) {
                long r = r0 + half*8;
                float v0 = acc[mi][ni][half*2    ] + bval.x;
                float v1 = acc[mi][ni][half*2 + 1] + bval.y;
                if (EPI == 1) {
                    v0 = gelu_exact(v0); v1 = gelu_exact(v1);
                    bf16 h0, l0, h1, l1;
                    split2(v0, h0, l0); split2(v1, h1, l1);
                    __nv_bfloat162 ph; ph.x = h0; ph.y = h1;
                    __nv_bfloat162 pl; pl.x = l0; pl.y = l1;
                    *(__nv_bfloat162*)(Ch + r*(long)N + c) = ph;
                    *(__nv_bfloat162*)(Cl + r*(long)N + c) = pl;
                } else {
                    if (EPI == 2) {
                        float2 rv = *(const float2*)(resid + r*(long)N + c);
                        v0 = rv.x + scale*v0;
                        v1 = rv.y + scale*v1;
                    }
                    float2 w = make_float2(v0, v1);
                    *(float2*)(C + r*(long)N + c) = w;
                }
            }
        }
    }
}

// ---------------- causal attention (flash-style, fp32) -> hi/lo out ----------
__global__ __launch_bounds__(64)
void attention_k(const float* __restrict__ qkv, bf16* __restrict__ oh,
                 bf16* __restrict__ ol) {
    const int mt = blockIdx.x;
    const int bh_ = blockIdx.y;
    const int b = bh_ / HH, h = bh_ % HH;
    const int tid = threadIdx.x;
    const int r = mt*64 + tid;
    const float* base = qkv + (long)(b*SS)*QKVN + h*HSZ;

    float q[64];
    {
        const float4* qp = (const float4*)(base + (long)r*QKVN);
        #pragma unroll
        for (int i = 0; i < 16; i++) {
            float4 t = qp[i];
            q[4*i] = t.x; q[4*i+1] = t.y; q[4*i+2] = t.z; q[4*i+3] = t.w;
        }
    }

    __shared__ float ks[64][64];
    __shared__ float vs[64][64];
    float m_i = -1e30f, l_i = 0.f;
    float acc[64];
    #pragma unroll
    for (int e = 0; e < 64; e++) acc[e] = 0.f;

    const int lr = tid >> 4;
    const int lc = (tid & 15) * 4;

    for (int kt = 0; kt <= mt; kt++) {
        __syncthreads();
        #pragma unroll
        for (int p = 0; p < 16; p++) {
            int row = p*4 + lr;
            const float* kp = base + (long)(kt*64 + row)*QKVN + DD + lc;
            const float* vp = base + (long)(kt*64 + row)*QKVN + 2*DD + lc;
            *(float4*)&ks[row][lc] = *(const float4*)kp;
            *(float4*)&vs[row][lc] = *(const float4*)vp;
        }
        __syncthreads();
        int tmax = (kt == mt) ? (tid + 1) : 64;
        for (int t = 0; t < tmax; t++) {
            float s = 0.f;
            #pragma unroll
            for (int d4 = 0; d4 < 16; d4++) {
                float4 kk = *(const float4*)&ks[t][d4*4];
                s += q[d4*4]*kk.x + q[d4*4+1]*kk.y + q[d4*4+2]*kk.z + q[d4*4+3]*kk.w;
            }
            s *= INV_SQRT_HS;
            if (s > m_i) {
                float corr = __expf(m_i - s);
                m_i = s;
                l_i = l_i*corr + 1.f;
                #pragma unroll
                for (int e4 = 0; e4 < 16; e4++) {
                    float4 vv = *(const float4*)&vs[t][e4*4];
                    acc[e4*4  ] = acc[e4*4  ]*corr + vv.x;
                    acc[e4*4+1] = acc[e4*4+1]*corr + vv.y;
                    acc[e4*4+2] = acc[e4*4+2]*corr + vv.z;
                    acc[e4*4+3] = acc[e4*4+3]*corr + vv.w;
                }
            } else {
                float p = __expf(s - m_i);
                l_i += p;
                #pragma unroll
                for (int e4 = 0; e4 < 16; e4++) {
                    float4 vv = *(const float4*)&vs[t][e4*4];
                    acc[e4*4  ] += p*vv.x;
                    acc[e4*4+1] += p*vv.y;
                    acc[e4*4+2] += p*vv.z;
                    acc[e4*4+3] += p*vv.w;
                }
            }
        }
    }

    float inv = 1.f / l_i;
    long obase = (long)(b*SS + r)*DD + h*HSZ;
    #pragma unroll
    for (int e = 0; e < 64; e++) {
        bf16 hi, lo; split2(acc[e]*inv, hi, lo);
        oh[obase + e] = hi; ol[obase + e] = lo;
    }
}

// ---------------- loss ----------------
__global__ void zero_loss_k() { g_loss_sum = 0.f; }

__global__ __launch_bounds__(256)
void loss_rows_k(const float* __restrict__ logits, const int* __restrict__ targets) {
    const int row = blockIdx.x;
    const int tid = threadIdx.x;
    const float* lr = logits + (long)row*VV;
    float m = -1e30f, l = 0.f;
    for (int c = tid; c < VV; c += 256) {
        float v = lr[c];
        if (v > m) { l = l*__expf(m - v) + 1.f; m = v; }
        else       { l += __expf(v - m); }
    }
    #pragma unroll
    for (int off = 16; off > 0; off >>= 1) {
        float m2 = __shfl_xor_sync(0xffffffffu, m, off);
        float l2 = __shfl_xor_sync(0xffffffffu, l, off);
        float M = fmaxf(m, m2);
        l = l*__expf(m - M) + l2*__expf(m2 - M);
        m = M;
    }
    __shared__ float sm_m[8], sm_l[8];
    int warp = tid >> 5, lane = tid & 31;
    if (lane == 0) { sm_m[warp] = m; sm_l[warp] = l; }
    __syncthreads();
    if (tid < 32) {
        float mm = (lane < 8) ? sm_m[lane] : -1e30f;
        float ll = (lane < 8) ? sm_l[lane] : 0.f;
        #pragma unroll
        for (int off = 4; off > 0; off >>= 1) {
            float m2 = __shfl_xor_sync(0xffffffffu, mm, off);
            float l2 = __shfl_xor_sync(0xffffffffu, ll, off);
            float M = fmaxf(mm, m2);
            ll = ll*__expf(mm - M) + l2*__expf(m2 - M);
            mm = M;
        }
        if (lane == 0) {
            float lse = logf(ll) + mm;
            int tgt = targets[row];
            atomicAdd(&g_loss_sum, lse - lr[tgt]);
        }
    }
}

__global__ void finalize_loss_k(float* __restrict__ out) {
    out[0] = g_loss_sum * (1.0f / (float)MR);
}

// ---------------- launch ----------------
extern "C" void kernel_launch(void* const* d_in, const int* in_sizes, int n_in,
                              void* d_out, int out_size) {
    const int*   idx     = (const int*)  d_in[0];
    const int*   targets = (const int*)  d_in[1];
    const float* tok     = (const float*)d_in[2];
    const float* pos     = (const float*)d_in[3];
    const float* Wq      = (const float*)d_in[4];
    const float* bq      = (const float*)d_in[5];
    const float* Wk      = (const float*)d_in[6];
    const float* bk      = (const float*)d_in[7];
    const float* Wv      = (const float*)d_in[8];
    const float* bv      = (const float*)d_in[9];
    const float* Wo      = (const float*)d_in[10];
    const float* bo      = (const float*)d_in[11];
    const float* ln1g    = (const float*)d_in[12];
    const float* ln1b    = (const float*)d_in[13];
    const float* ln2g    = (const float*)d_in[14];
    const float* ln2b    = (const float*)d_in[15];
    const float* W1      = (const float*)d_in[16];
    const float* b1      = (const float*)d_in[17];
    const float* W2      = (const float*)d_in[18];
    const float* b2      = (const float*)d_in[19];
    const float* W3      = (const float*)d_in[20];
    const float* b3      = (const float*)d_in[21];
    const float* att_s   = (const float*)d_in[22];
    const float* ffd_s   = (const float*)d_in[23];
    const float* lnfg    = (const float*)d_in[24];
    const float* lnfb    = (const float*)d_in[25];
    float* out = (float*)d_out;

    float *x, *qkvb, *bp;
    bf16 *hh, *hl, *oh, *ol, *f1h, *f1l, *f2h, *f2l;
    bf16 *Wqkvh, *Wqkvl, *Woh, *Wol, *W1h, *W1l, *W2h, *W2l, *W3h, *W3l, *tokh, *tokl;
    cudaGetSymbolAddress((void**)&x,    g_x);
    cudaGetSymbolAddress((void**)&qkvb, g_qkv);
    cudaGetSymbolAddress((void**)&bp,   g_bqkv);
    cudaGetSymbolAddress((void**)&hh,   g_h_h);   cudaGetSymbolAddress((void**)&hl,  g_h_l);
    cudaGetSymbolAddress((void**)&oh,   g_o_h);   cudaGetSymbolAddress((void**)&ol,  g_o_l);
    cudaGetSymbolAddress((void**)&f1h,  g_f1_h);  cudaGetSymbolAddress((void**)&f1l, g_f1_l);
    cudaGetSymbolAddress((void**)&f2h,  g_f2_h);  cudaGetSymbolAddress((void**)&f2l, g_f2_l);
    cudaGetSymbolAddress((void**)&Wqkvh,g_Wqkv_h);cudaGetSymbolAddress((void**)&Wqkvl,g_Wqkv_l);
    cudaGetSymbolAddress((void**)&Woh,  g_Wo_h);  cudaGetSymbolAddress((void**)&Wol, g_Wo_l);
    cudaGetSymbolAddress((void**)&W1h,  g_W1_h);  cudaGetSymbolAddress((void**)&W1l, g_W1_l);
    cudaGetSymbolAddress((void**)&W2h,  g_W2_h);  cudaGetSymbolAddress((void**)&W2l, g_W2_l);
    cudaGetSymbolAddress((void**)&W3h,  g_W3_h);  cudaGetSymbolAddress((void**)&W3l, g_W3_l);
    cudaGetSymbolAddress((void**)&tokh, g_tok_h); cudaGetSymbolAddress((void**)&tokl,g_tok_l);

    // weight prep (runs inside the graph; deterministic)
    {
        long n;
        n = (long)LL*DD*QKVN;
        pack_qkv_w<<<(unsigned)((n + 255)/256), 256>>>(Wq, Wk, Wv, Wqkvh, Wqkvl);
        pack_qkv_b<<<(LL*QKVN + 255)/256, 256>>>(bq, bk, bv, bp);
        n = (long)LL*DD*DD;   split_k<<<(unsigned)((n+255)/256),256>>>(Wo, Woh, Wol, n);
        n = (long)LL*DD*FF1;  split_k<<<(unsigned)((n+255)/256),256>>>(W1, W1h, W1l, n);
        n = (long)LL*FF1*FF2; split_k<<<(unsigned)((n+255)/256),256>>>(W2, W2h, W2l, n);
        n = (long)LL*FF2*DD;  split_k<<<(unsigned)((n+255)/256),256>>>(W3, W3h, W3l, n);
        n = (long)VV*DD;      split_k<<<(unsigned)((n+255)/256),256>>>(tok, tokh, tokl, n);
    }

    embed_k<<<(MR*DD + 255)/256, 256>>>(idx, tok, pos, x);

    for (int l = 0; l < LL; l++) {
        layernorm_k<<<MR, 256>>>(x, hh, hl, ln1g + (long)l*DD, ln1b + (long)l*DD);
        bgemm_k<0,false><<<dim3(QKVN/128, MR/128), 256>>>(
            hh, hl, Wqkvh + (long)l*DD*QKVN, Wqkvl + (long)l*DD*QKVN,
            bp + (long)l*QKVN, qkvb, nullptr, nullptr, nullptr, nullptr,
            MR, QKVN, DD);
        attention_k<<<dim3(SS/64, BB*HH), 64>>>(qkvb, oh, ol);
        bgemm_k<2,false><<<dim3(DD/128, MR/128), 256>>>(
            oh, ol, Woh + (long)l*DD*DD, Wol + (long)l*DD*DD,
            bo + (long)l*DD, x, nullptr, nullptr, x, att_s + l,
            MR, DD, DD);
        layernorm_k<<<MR, 256>>>(x, hh, hl, ln2g + (long)l*DD, ln2b + (long)l*DD);
        bgemm_k<1,false><<<dim3(FF1/128, MR/128), 256>>>(
            hh, hl, W1h + (long)l*DD*FF1, W1l + (long)l*DD*FF1,
            b1 + (long)l*FF1, nullptr, f1h, f1l, nullptr, nullptr,
            MR, FF1, DD);
        bgemm_k<1,false><<<dim3(FF2/128, MR/128), 256>>>(
            f1h, f1l, W2h + (long)l*FF1*FF2, W2l + (long)l*FF1*FF2,
            b2 + (long)l*FF2, nullptr, f2h, f2l, nullptr, nullptr,
            MR, FF2, FF1);
        bgemm_k<2,false><<<dim3(DD/128, MR/128), 256>>>(
            f2h, f2l, W3h + (long)l*FF2*DD, W3l + (long)l*FF2*DD,
            b3 + (long)l*DD, x, nullptr, nullptr, x, ffd_s + l,
            MR, DD, FF2);
    }

    layernorm_k<<<MR, 256>>>(x, hh, hl, lnfg, lnfb);

    // logits = h @ tok^T -> directly into d_out
    bgemm_k<3,true><<<dim3(VV/128, MR/128), 256>>>(
        hh, hl, tokh, tokl, nullptr, out, nullptr, nullptr, nullptr, nullptr,
        MR, VV, DD);

    // loss
    zero_loss_k<<<1,1>>>();
    loss_rows_k<<<MR, 256>>>(out, targets);
    if (out_size > MR*(long)VV) {
        finalize_loss_k<<<1,1>>>(out + (long)MR*VV);
    }
}